// round 6
// baseline (speedup 1.0000x reference)
#include <cuda_runtime.h>

// ---------------- constants ----------------
#define C_NUM   80
#define TOPK_N  1000
#define CONF_T  0.05f
#define NMS_THR 0.6f
#define IMG_INV (1.0f/2048.0f)
#define HBINS   16384
#define CAND_CAP 65536
#define N_ALL   3000
#define ROWS0   196608
#define ROWS1   49152
#define ROWS2   12288
#define RTOT    258048
#define NMS_CAP 1024

// ---------------- device scratch ----------------
__device__ float              g_b[RTOT];
__device__ unsigned int       g_hist[3 * HBINS];
__device__ unsigned int       g_cnt[3];
__device__ unsigned int       g_Tbin[3];
__device__ unsigned long long g_cand[3][CAND_CAP];
__device__ unsigned long long g_topk[3][TOPK_N];

__device__ __forceinline__ float sigm(float x) { return 1.0f / (1.0f + expf(-x)); }

__device__ __forceinline__ void level_of(int grow, int& lvl, int& r) {
    if (grow < ROWS0)              { lvl = 0; r = grow; }
    else if (grow < ROWS0 + ROWS1) { lvl = 1; r = grow - ROWS0; }
    else                           { lvl = 2; r = grow - ROWS0 - ROWS1; }
}

__device__ void bitonic_desc(unsigned long long* s, int n) {
    for (int k = 2; k <= n; k <<= 1) {
        for (int j = k >> 1; j > 0; j >>= 1) {
            for (int t = threadIdx.x; t < n; t += blockDim.x) {
                int l = t ^ j;
                if (l > t) {
                    unsigned long long a = s[t], b = s[l];
                    bool dir = ((t & k) == 0);
                    if (dir ? (a < b) : (a > b)) { s[t] = b; s[l] = a; }
                }
            }
            __syncthreads();
        }
    }
}

// ============ K1: per-anchor bound + histogram (4 threads/row) ============
__global__ void k_rowmax(const float* __restrict__ obj0, const float* __restrict__ cls0,
                         const float* __restrict__ obj1, const float* __restrict__ cls1,
                         const float* __restrict__ obj2, const float* __restrict__ cls2) {
    int g = blockIdx.x * blockDim.x + threadIdx.x;
    int grow = g >> 2;
    int sub = g & 3;
    if (grow >= RTOT) return;
    int lvl, r;
    level_of(grow, lvl, r);
    const float* cls = (lvl == 0) ? cls0 : ((lvl == 1) ? cls1 : cls2);
    const float4* c4 = reinterpret_cast<const float4*>(cls) + (size_t)r * 20;
    float mx = -1e30f;
#pragma unroll
    for (int it = 0; it < 5; it++) {
        float4 v = c4[it * 4 + sub];
        mx = fmaxf(mx, fmaxf(fmaxf(v.x, v.y), fmaxf(v.z, v.w)));
    }
    mx = fmaxf(mx, __shfl_xor_sync(0xFFFFFFFFu, mx, 1));
    mx = fmaxf(mx, __shfl_xor_sync(0xFFFFFFFFu, mx, 2));
    if (sub == 0) {
        const float* obj = (lvl == 0) ? obj0 : ((lvl == 1) ? obj1 : obj2);
        float b = sqrtf(sigm(obj[r]) * sigm(mx));
        g_b[grow] = b;
        int bin = (int)(b * (float)HBINS);
        if (bin > HBINS - 1) bin = HBINS - 1;
        atomicAdd(&g_hist[lvl * HBINS + bin], 1u);
    }
}

// ============ K2: per-level threshold bin (3 blocks) ============
__global__ void k_findT() {
    int lvl = blockIdx.x;
    __shared__ unsigned int csum[256];
    __shared__ unsigned int cbins[64];
    __shared__ int s_ch;
    __shared__ unsigned int s_cum;
    unsigned int s = 0;
    int base = lvl * HBINS + threadIdx.x * 64;
#pragma unroll 8
    for (int i = 0; i < 64; i++) s += g_hist[base + i];
    csum[threadIdx.x] = s;
    __syncthreads();
    if (threadIdx.x == 0) {
        unsigned int cum = 0;
        int ch = 255;
        for (; ch > 0; ch--) {
            if (cum + csum[ch] >= TOPK_N) break;
            cum += csum[ch];
        }
        s_ch = ch;
        s_cum = cum;
    }
    __syncthreads();
    int ch = s_ch;
    if (threadIdx.x < 64)
        cbins[threadIdx.x] = g_hist[lvl * HBINS + ch * 64 + threadIdx.x];
    __syncthreads();
    if (threadIdx.x == 0) {
        unsigned int cum = s_cum;
        int bin = 63;
        for (; bin > 0; bin--) {
            cum += cbins[bin];
            if (cum >= TOPK_N) break;
        }
        g_Tbin[lvl] = (unsigned int)(ch * 64 + bin);
        g_cnt[lvl] = 0u;
    }
}

// ============ K3: sparse expansion, 1 thread/row, prefetched ============
__global__ void k_compact(const float* __restrict__ obj0, const float* __restrict__ cls0,
                          const float* __restrict__ obj1, const float* __restrict__ cls1,
                          const float* __restrict__ obj2, const float* __restrict__ cls2) {
    __shared__ unsigned int sT[3];
    if (threadIdx.x < 3) sT[threadIdx.x] = g_Tbin[threadIdx.x];
    __syncthreads();
    int grow = blockIdx.x * blockDim.x + threadIdx.x;
    if (grow >= RTOT) return;
    int lvl, r;
    level_of(grow, lvl, r);
    int B = (int)sT[lvl];
    if ((int)(g_b[grow] * (float)HBINS) < B) return;  // exact same discretization as K1
    const float* obj = (lvl == 0) ? obj0 : ((lvl == 1) ? obj1 : obj2);
    const float* cls = (lvl == 0) ? cls0 : ((lvl == 1) ? cls1 : cls2);
    float so = sigm(obj[r]);
    const float4* c4 = reinterpret_cast<const float4*>(cls) + (size_t)r * 20;
    float4 vbuf[20];
#pragma unroll
    for (int j = 0; j < 20; j++) vbuf[j] = c4[j];  // MLP=20, one latency exposure
#pragma unroll
    for (int j = 0; j < 20; j++) {
        float vv[4] = {vbuf[j].x, vbuf[j].y, vbuf[j].z, vbuf[j].w};
#pragma unroll
        for (int k = 0; k < 4; k++) {
            float s = sqrtf(so * sigm(vv[k]));
            if ((int)(s * (float)HBINS) >= B) {
                unsigned int p = atomicAdd(&g_cnt[lvl], 1u);
                if (p < CAND_CAP) {
                    int idx = r * C_NUM + j * 4 + k;
                    g_cand[lvl][p] = ((unsigned long long)__float_as_uint(s) << 24) |
                                     (unsigned long long)(0xFFFFFF - idx);
                }
            }
        }
    }
}

// ============ K4: per-level exact radix select + top-1000 sort (3 blocks) ============
__global__ __launch_bounds__(1024, 1)
void k_select() {
    __shared__ unsigned int hist[256];
    __shared__ unsigned int s_chunk[8];
    __shared__ int s_v;
    __shared__ unsigned int s_wantnew, s_histv, s_m;
    __shared__ unsigned long long keys[1024];
    int tid = threadIdx.x;
    int lvl = blockIdx.x;
    unsigned int cnt = g_cnt[lvl];
    if (cnt > CAND_CAP) cnt = CAND_CAP;
    const unsigned long long* cand = g_cand[lvl];

    unsigned long long prefix = 0ULL, mask = 0ULL;
    unsigned int want = TOPK_N;
    bool done = false;
    for (int p = 7; p >= 0 && !done; p--) {
        for (int i = tid; i < 256; i += 1024) hist[i] = 0u;
        __syncthreads();
        int sh = p * 8;
        for (int i = tid; i < (int)cnt; i += 1024) {
            unsigned long long k = cand[i];
            if ((k & mask) == prefix)
                atomicAdd(&hist[(unsigned int)((k >> sh) & 255ULL)], 1u);
        }
        __syncthreads();
        if (tid < 256) {
            unsigned int ws = hist[tid];
            for (int o = 16; o > 0; o >>= 1)
                ws += __shfl_down_sync(0xFFFFFFFFu, ws, o);
            if ((tid & 31) == 0) s_chunk[tid >> 5] = ws;
        }
        __syncthreads();
        if (tid == 0) {
            unsigned int cum = 0;
            int ch = 7;
            for (; ch > 0; ch--) {
                if (cum + s_chunk[ch] >= want) break;
                cum += s_chunk[ch];
            }
            int v = ch * 32 + 31;
            for (; v > ch * 32; v--) {
                if (cum + hist[v] >= want) break;
                cum += hist[v];
            }
            s_v = v;
            s_wantnew = want - cum;
            s_histv = hist[v];
        }
        __syncthreads();
        prefix |= ((unsigned long long)s_v) << sh;
        mask   |= 0xFFULL << sh;
        want = s_wantnew;
        if (want == s_histv) done = true;
        __syncthreads();
    }
    unsigned long long Kstar = prefix;

    if (tid == 0) s_m = 0u;
    __syncthreads();
    for (int i = tid; i < (int)cnt; i += 1024) {
        unsigned long long k = cand[i];
        if (k >= Kstar) {
            unsigned int p = atomicAdd(&s_m, 1u);
            if (p < 1024u) keys[p] = k;
        }
    }
    __syncthreads();
    if (tid >= (int)min(s_m, 1024u)) keys[tid] = 0ULL;
    __syncthreads();
    bitonic_desc(keys, 1024);
    if (tid < TOPK_N) g_topk[lvl][tid] = keys[tid];
}

// ============ K5: per-class decode + merge-rank + NMS + output (80 blocks) ============
extern __shared__ unsigned char dyn5[];

__global__ __launch_bounds__(256, 1)
void k_nms(const float* __restrict__ r0, const float* __restrict__ r1,
           const float* __restrict__ r2, const float* __restrict__ anc,
           float* __restrict__ out) {
    int tid = threadIdx.x;
    int c = blockIdx.x;

    // zero histogram for the next graph replay (any order vs rest of kernel is fine)
    for (int i = c * 256 + tid; i < 3 * HBINS; i += 80 * 256) g_hist[i] = 0u;

    unsigned long long* gk   = (unsigned long long*)dyn5;                 // 3000*8
    unsigned char*      lab  = (unsigned char*)(dyn5 + 24000);            // 3000
    unsigned long long* lg   = (unsigned long long*)(dyn5 + 27008);       // 1024*8
    float4*             lbox = (float4*)(dyn5 + 27008 + 8192);            // 1024*16
    float*              lare = (float*)(dyn5 + 27008 + 8192 + 16384);     // 1024*4
    int*                lrnk = (int*)(dyn5 + 27008 + 8192 + 16384 + 4096);// 1024*4
    unsigned char*      lsup = (unsigned char*)(dyn5 + 27008 + 8192 + 16384 + 8192);
    __shared__ unsigned int s_n;
    __shared__ float s_anc[18];
    if (tid == 0) s_n = 0u;
    if (tid < 18) s_anc[tid] = anc[tid];

    // build composite keys + labels for all 3000
    for (int i = tid; i < N_ALL; i += 256) {
        int lvl = i / TOPK_N;
        unsigned long long key = g_topk[lvl][i - lvl * TOPK_N];
        unsigned int sb = (unsigned int)(key >> 24);
        float s = __uint_as_float(sb);
        unsigned int zs = (s > CONF_T) ? sb : 0u;
        gk[i] = ((unsigned long long)zs << 12) | (unsigned long long)(4095 - i);
        int idx = 0xFFFFFF - (int)(key & 0xFFFFFFULL);
        lab[i] = (unsigned char)(idx % C_NUM);
    }
    __syncthreads();

    // gather this class's entries (including zero-score ones: they still own outputs)
    for (int i = tid; i < N_ALL; i += 256) {
        if (lab[i] == (unsigned char)c) {
            unsigned int p = atomicAdd(&s_n, 1u);
            if (p < NMS_CAP) lg[p] = gk[i];
        }
    }
    __syncthreads();
    unsigned int n = min(s_n, (unsigned int)NMS_CAP);
    for (int i = (int)n + tid; i < NMS_CAP; i += 256) lg[i] = 0ULL;
    __syncthreads();
    bitonic_desc(lg, NMS_CAP);   // desc by composite key == global score order

    // decode + rank + write static outputs
    float offv = (float)c * 100000.0f;
    for (int j = tid; j < (int)n; j += 256) {
        unsigned long long gkv = lg[j];
        int i = 4095 - (int)(gkv & 0xFFFULL);
        int lvl = i / TOPK_N;
        int r = i - lvl * TOPK_N;
        unsigned long long key = g_topk[lvl][r];
        // global rank: own-level position + lower-bounds in other level segments
        int rank = r;
#pragma unroll
        for (int l = 0; l < 3; l++) {
            if (l == lvl) continue;
            const unsigned long long* arr = gk + l * TOPK_N;
            int lo = 0, hi = TOPK_N;
            while (lo < hi) {
                int mid = (lo + hi) >> 1;
                if (arr[mid] > gkv) lo = mid + 1; else hi = mid;
            }
            rank += lo;
        }
        int idx = 0xFFFFFF - (int)(key & 0xFFFFFFULL);
        int m = idx / C_NUM;
        int a = m % 3;
        int cell = m / 3;
        int W = (lvl == 0) ? 256 : ((lvl == 1) ? 128 : 64);
        float stride = (lvl == 0) ? 8.0f : ((lvl == 1) ? 16.0f : 32.0f);
        int x = cell % W, y = cell / W;
        const float* reg = ((lvl == 0) ? r0 : ((lvl == 1) ? r1 : r2)) + (size_t)m * 4;
        float cx = ((float)x + 0.5f) * stride + (sigm(reg[0]) * 3.0f - 1.5f) * stride;
        float cy = ((float)y + 0.5f) * stride + (sigm(reg[1]) * 3.0f - 1.5f) * stride;
        float bw = expf(reg[2]) * s_anc[lvl * 6 + a * 2 + 0];
        float bh = expf(reg[3]) * s_anc[lvl * 6 + a * 2 + 1];
        float4 b;
        b.x = cx - 0.5f * bw; b.y = cy - 0.5f * bh;
        b.z = cx + 0.5f * bw; b.w = cy + 0.5f * bh;
        out[rank * 4 + 0] = fminf(fmaxf(b.x * IMG_INV, 0.0f), 1.0f);
        out[rank * 4 + 1] = fminf(fmaxf(b.y * IMG_INV, 0.0f), 1.0f);
        out[rank * 4 + 2] = fminf(fmaxf(b.z * IMG_INV, 0.0f), 1.0f);
        out[rank * 4 + 3] = fminf(fmaxf(b.w * IMG_INV, 0.0f), 1.0f);
        out[12000 + rank] = 0.0f;
        out[15000 + rank] = (float)c;
        // offset-quantized boxes, exactly like reference (f32 box + label*1e5)
        float4 ob;
        ob.x = b.x + offv; ob.y = b.y + offv; ob.z = b.z + offv; ob.w = b.w + offv;
        lbox[j] = ob;
        lare[j] = (ob.z - ob.x) * (ob.w - ob.y);
        lrnk[j] = rank;
        lsup[j] = 0;
    }
    __syncthreads();

    // greedy NMS in global-score order within this class
    for (int a = 0; a < (int)n; a++) {
        float sa = __uint_as_float((unsigned int)(lg[a] >> 12));
        bool keep = (!lsup[a]) && (sa > CONF_T);
        if (keep) {
            if (tid == 0) out[12000 + lrnk[a]] = sa;
            float4 A = lbox[a];
            float arA = lare[a];
            for (int b = a + 1 + tid; b < (int)n; b += 256) {
                if (lsup[b]) continue;
                float4 B = lbox[b];
                float ltx = fmaxf(A.x, B.x), lty = fmaxf(A.y, B.y);
                float rbx = fminf(A.z, B.z), rby = fminf(A.w, B.w);
                float wx = fmaxf(rbx - ltx, 0.0f), wy = fmaxf(rby - lty, 0.0f);
                float inter = wx * wy;
                float iou = inter / (arA + lare[b] - inter + 1e-12f);
                if (iou > NMS_THR) lsup[b] = 1;
            }
        }
        __syncthreads();
    }
}

// ---------------- launcher ----------------
extern "C" void kernel_launch(void* const* d_in, const int* in_sizes, int n_in,
                              void* d_out, int out_size) {
    (void)in_sizes; (void)n_in; (void)out_size;
    const float* obj0 = (const float*)d_in[0];
    const float* cls0 = (const float*)d_in[1];
    const float* reg0 = (const float*)d_in[2];
    const float* obj1 = (const float*)d_in[3];
    const float* cls1 = (const float*)d_in[4];
    const float* reg1 = (const float*)d_in[5];
    const float* obj2 = (const float*)d_in[6];
    const float* cls2 = (const float*)d_in[7];
    const float* reg2 = (const float*)d_in[8];
    const float* anc  = (const float*)d_in[9];
    float* out = (float*)d_out;

    const int DYN5 = 24000 + 3008 + 8192 + 16384 + 4096 + 4096 + 1024;  // ~60.8 KB
    cudaFuncSetAttribute(k_nms, cudaFuncAttributeMaxDynamicSharedMemorySize, DYN5);

    k_rowmax<<<(RTOT * 4 + 255) / 256, 256>>>(obj0, cls0, obj1, cls1, obj2, cls2);
    k_findT<<<3, 256>>>();
    k_compact<<<(RTOT + 255) / 256, 256>>>(obj0, cls0, obj1, cls1, obj2, cls2);
    k_select<<<3, 1024>>>();
    k_nms<<<80, 256, DYN5>>>(reg0, reg1, reg2, anc, out);
}